// round 1
// baseline (speedup 1.0000x reference)
#include <cuda_runtime.h>
#include <math.h>

#define FULL 0xFFFFFFFFu

// ---------------- scratch (device globals; no allocation allowed) -------------
__device__ float g_ada[2 * 256];                 // [B, 2C] scale|shift
__device__ float g_q[2 * 4 * 64 * 64 * 32];      // [B,n,H,W,d]
__device__ float g_k[2 * 4 * 64 * 64 * 32];
__device__ float g_v[2 * 4 * 64 * 64 * 32];
__device__ float g_att[2 * 64 * 64 * 128];       // [B,H,W,C]

__device__ __forceinline__ int nb_start(int i) {
    int s = i - 3;
    s = s < 0 ? 0 : s;
    return s > 57 ? 57 : s;   // L-K = 64-7
}

// ---------------- kernel A: sinusoidal emb + silu + adaLN MLP -----------------
// grid(2), block(256). g_ada[b][j] = silu(emb[b]) @ ln_w[:,j] + ln_b[j]
__global__ void adaln_kernel(const int* __restrict__ t,
                             const float* __restrict__ ln_w,
                             const float* __restrict__ ln_b) {
    __shared__ float s_silu[128];
    const int b = blockIdx.x;
    const int tid = threadIdx.x;
    const float tf = (float)t[b] * 40.0f;              // t/100*4000
    if (tid < 64) {
        // freq = exp(-i * ln(10000)/63)
        float f = __expf(-(float)tid * (9.210340371976184f / 63.0f));
        float e = tf * f;
        float se = sinf(e), ce = cosf(e);
        s_silu[tid]      = se / (1.0f + __expf(-se));
        s_silu[tid + 64] = ce / (1.0f + __expf(-ce));
    }
    __syncthreads();
    const int j = tid;                                  // 0..255
    float acc = ln_b[j];
#pragma unroll 8
    for (int k = 0; k < 128; k++) acc += s_silu[k] * ln_w[k * 256 + j];
    g_ada[b * 256 + j] = acc;
}

// ---------------- kernel B: LayerNorm + modulate + qkv GEMM -------------------
// grid(256), block(256). 32 rows/block, out [32,384] register-tiled 4x12.
__global__ void ln_qkv_kernel(const float* __restrict__ x,
                              const float* __restrict__ qkv_w,
                              const float* __restrict__ qkv_b) {
    __shared__ float sy[32][128];
    __shared__ float sw[16][384];
    __shared__ float s_scale[128], s_shift[128];

    const int tid = threadIdx.x;
    const int row0 = blockIdx.x * 32;
    const int b = row0 >> 12;                // 4096 rows per batch; 32 | 4096

    if (tid < 128) s_scale[tid] = g_ada[b * 256 + tid];
    else           s_shift[tid - 128] = g_ada[b * 256 + tid];
    __syncthreads();

    const int warp = tid >> 5, lane = tid & 31;

    // --- LayerNorm: each warp handles 4 rows ---
    for (int i = 0; i < 4; i++) {
        const int r = warp * 4 + i;
        const float4 xv = *(const float4*)(x + (row0 + r) * 128 + lane * 4);
        float sum = xv.x + xv.y + xv.z + xv.w;
        float sq  = xv.x * xv.x + xv.y * xv.y + xv.z * xv.z + xv.w * xv.w;
#pragma unroll
        for (int o = 16; o; o >>= 1) {
            sum += __shfl_xor_sync(FULL, sum, o);
            sq  += __shfl_xor_sync(FULL, sq, o);
        }
        const float mean = sum * (1.0f / 128.0f);
        const float var  = sq * (1.0f / 128.0f) - mean * mean;
        const float rstd = rsqrtf(var + 1e-5f);
        const int c0 = lane * 4;
        float4 yv;
        yv.x = (xv.x - mean) * rstd * (1.0f + s_scale[c0 + 0]) + s_shift[c0 + 0];
        yv.y = (xv.y - mean) * rstd * (1.0f + s_scale[c0 + 1]) + s_shift[c0 + 1];
        yv.z = (xv.z - mean) * rstd * (1.0f + s_scale[c0 + 2]) + s_shift[c0 + 2];
        yv.w = (xv.w - mean) * rstd * (1.0f + s_scale[c0 + 3]) + s_shift[c0 + 3];
        *(float4*)&sy[r][c0] = yv;
    }
    __syncthreads();

    // --- GEMM [32,128] x [128,384]: thread = 4 rows x 12 cols ---
    float acc[4][12];
#pragma unroll
    for (int i = 0; i < 4; i++)
#pragma unroll
        for (int cc = 0; cc < 12; cc++) acc[i][cc] = 0.0f;

    const int rg = warp;   // rows 4*rg .. 4*rg+3
    for (int kc = 0; kc < 128; kc += 16) {
        for (int i = tid; i < 16 * 384; i += 256) {
            int kk = i / 384, j = i - kk * 384;
            sw[kk][j] = qkv_w[(kc + kk) * 384 + j];
        }
        __syncthreads();
#pragma unroll
        for (int kk = 0; kk < 16; kk++) {
            float y0 = sy[rg * 4 + 0][kc + kk];
            float y1 = sy[rg * 4 + 1][kc + kk];
            float y2 = sy[rg * 4 + 2][kc + kk];
            float y3 = sy[rg * 4 + 3][kc + kk];
            float wv[12];
#pragma unroll
            for (int cc = 0; cc < 12; cc++) wv[cc] = sw[kk][lane + 32 * cc];
#pragma unroll
            for (int cc = 0; cc < 12; cc++) {
                acc[0][cc] += y0 * wv[cc];
                acc[1][cc] += y1 * wv[cc];
                acc[2][cc] += y2 * wv[cc];
                acc[3][cc] += y3 * wv[cc];
            }
        }
        __syncthreads();
    }

    // --- scatter to q/k/v in [B,n,H,W,d] ---
    const float qscale = 0.17677669529663687f;   // 32^-0.5
#pragma unroll
    for (int i = 0; i < 4; i++) {
        const int row = row0 + rg * 4 + i;
        const int bb = row >> 12, hh = (row >> 6) & 63, ww = row & 63;
#pragma unroll
        for (int cc = 0; cc < 12; cc++) {
            const int j = lane + 32 * cc;
            float val = acc[i][cc] + qkv_b[j];
            const int which = j >> 7;
            const int rem = j & 127;
            const int n = rem >> 5, d = rem & 31;
            const int idx = (((bb * 4 + n) * 64 + hh) * 64 + ww) * 32 + d;
            if (which == 0)      g_q[idx] = val * qscale;
            else if (which == 1) g_k[idx] = val;
            else                 g_v[idx] = val;
        }
    }
}

// ---------------- kernel C: 7x7 neighborhood attention ------------------------
// grid(4, 64, 8) = (w-tile, h, b*4+n). block 128 = 4 warps, 4 queries/warp.
// One warp per query, lane = head-dim. Online softmax over 49 keys.
__global__ void natten_kernel(const float* __restrict__ rpb) {
    __shared__ float ks[7 * 22 * 32];
    __shared__ float vs[7 * 22 * 32];
    __shared__ float srpb[169];

    const int tid = threadIdx.x;
    const int w0 = blockIdx.x * 16;
    const int h  = blockIdx.y;
    const int bn = blockIdx.z;            // b*4+n
    const int b = bn >> 2, n = bn & 3;

    const int cs = nb_start(w0);
    const int ce = nb_start(w0 + 15) + 6;
    const int ncols = ce - cs + 1;        // 19 or 22
    const int hs = nb_start(h);
    const int base = bn * (64 * 64 * 32);

    const int total = 7 * ncols * 32;
    for (int i = tid; i < total; i += 128) {
        const int a = i / (ncols * 32);
        const int rem = i - a * (ncols * 32);
        const int g = base + (hs + a) * 2048 + cs * 32 + rem;
        ks[a * (22 * 32) + rem] = g_k[g];
        vs[a * (22 * 32) + rem] = g_v[g];
    }
    for (int i = tid; i < 169; i += 128) srpb[i] = rpb[n * 169 + i];
    __syncthreads();

    const int warp = tid >> 5, lane = tid & 31;
    for (int qi = 0; qi < 4; qi++) {
        const int w = w0 + warp * 4 + qi;
        const int ws = nb_start(w);
        const float qd = g_q[base + h * 2048 + w * 32 + lane];
        float m = -INFINITY, l = 0.0f, acc = 0.0f;
#pragma unroll
        for (int a = 0; a < 7; a++) {
            const int rb = (hs + a - h + 6) * 13 + (ws - w + 6);
            const int cb = (a * 22 + (ws - cs)) * 32 + lane;
#pragma unroll
            for (int c = 0; c < 7; c++) {
                float s = qd * ks[cb + c * 32];
#pragma unroll
                for (int o = 16; o; o >>= 1) s += __shfl_xor_sync(FULL, s, o);
                s += srpb[rb + c];
                const float mn = fmaxf(m, s);
                const float corr = __expf(m - mn);
                const float p = __expf(s - mn);
                l = l * corr + p;
                acc = acc * corr + p * vs[cb + c * 32];
                m = mn;
            }
        }
        g_att[((b * 64 + h) * 64 + w) * 128 + n * 32 + lane] = acc / l;
    }
}

// ---------------- kernel D: proj GEMM [8192,128]x[128,128] + bias -------------
// grid(256), block(256). 32 rows/block, thread = 4 rows x 4 cols.
__global__ void proj_kernel(const float* __restrict__ proj_w,
                            const float* __restrict__ proj_b,
                            float* __restrict__ out) {
    __shared__ float sa[32][128];
    __shared__ float sw[32][128];
    const int tid = threadIdx.x;
    const int row0 = blockIdx.x * 32;

    for (int i = tid; i < 32 * 128; i += 256)
        sa[i >> 7][i & 127] = g_att[row0 * 128 + i];

    const int warp = tid >> 5, lane = tid & 31;
    float acc[4][4] = {};

    for (int kc = 0; kc < 128; kc += 32) {
        __syncthreads();       // protects sw reuse; also orders sa load on iter 0
        for (int i = tid; i < 32 * 128; i += 256) {
            int kk = i >> 7, j = i & 127;
            sw[kk][j] = proj_w[(kc + kk) * 128 + j];
        }
        __syncthreads();
#pragma unroll
        for (int kk = 0; kk < 32; kk++) {
            float a0 = sa[warp * 4 + 0][kc + kk];
            float a1 = sa[warp * 4 + 1][kc + kk];
            float a2 = sa[warp * 4 + 2][kc + kk];
            float a3 = sa[warp * 4 + 3][kc + kk];
            float wv[4];
#pragma unroll
            for (int cc = 0; cc < 4; cc++) wv[cc] = sw[kk][lane + 32 * cc];
#pragma unroll
            for (int cc = 0; cc < 4; cc++) {
                acc[0][cc] += a0 * wv[cc];
                acc[1][cc] += a1 * wv[cc];
                acc[2][cc] += a2 * wv[cc];
                acc[3][cc] += a3 * wv[cc];
            }
        }
    }

#pragma unroll
    for (int i = 0; i < 4; i++) {
        const int row = row0 + warp * 4 + i;
#pragma unroll
        for (int cc = 0; cc < 4; cc++) {
            const int j = lane + 32 * cc;
            out[row * 128 + j] = acc[i][cc] + proj_b[j];
        }
    }
}

// ---------------- launch ------------------------------------------------------
extern "C" void kernel_launch(void* const* d_in, const int* in_sizes, int n_in,
                              void* d_out, int out_size) {
    const float* x      = (const float*)d_in[0];
    // d_in[1] = cond (unused)
    const int*   t      = (const int*)d_in[2];
    const float* ln_w   = (const float*)d_in[3];
    const float* ln_b   = (const float*)d_in[4];
    const float* qkv_w  = (const float*)d_in[5];
    const float* qkv_b  = (const float*)d_in[6];
    const float* rpb    = (const float*)d_in[7];
    const float* proj_w = (const float*)d_in[8];
    const float* proj_b = (const float*)d_in[9];
    float* out = (float*)d_out;

    adaln_kernel<<<2, 256>>>(t, ln_w, ln_b);
    ln_qkv_kernel<<<256, 256>>>(x, qkv_w, qkv_b);
    dim3 gatt(4, 64, 8);
    natten_kernel<<<gatt, 128>>>(rpb);
    proj_kernel<<<256, 256>>>(proj_w, proj_b, out);
}

// round 2
// speedup vs baseline: 1.6703x; 1.6703x over previous
#include <cuda_runtime.h>
#include <math.h>

#define FULL 0xFFFFFFFFu

// ---------------- scratch (device globals; no allocation allowed) -------------
__device__ float g_ada[2 * 256];                 // [B, 2C] scale|shift
__device__ float g_y[2 * 64 * 64 * 128];         // LN output [rows, C]
__device__ float g_q[2 * 4 * 64 * 64 * 32];      // [B,n,H,W,d]
__device__ float g_k[2 * 4 * 64 * 64 * 32];
__device__ float g_v[2 * 4 * 64 * 64 * 32];
__device__ float g_att[2 * 64 * 64 * 128];       // [B,H,W,C]

__device__ __forceinline__ int nb_start(int i) {
    int s = i - 3;
    s = s < 0 ? 0 : s;
    return s > 57 ? 57 : s;   // L-K = 64-7
}

// ---------------- kernel A: sinusoidal emb + silu + adaLN MLP -----------------
__global__ void adaln_kernel(const int* __restrict__ t,
                             const float* __restrict__ ln_w,
                             const float* __restrict__ ln_b) {
    __shared__ float s_silu[128];
    const int b = blockIdx.x;
    const int tid = threadIdx.x;
    const float tf = (float)t[b] * 40.0f;              // t/100*4000
    if (tid < 64) {
        float f = __expf(-(float)tid * (9.210340371976184f / 63.0f));
        float e = tf * f;
        float se = sinf(e), ce = cosf(e);
        s_silu[tid]      = se / (1.0f + __expf(-se));
        s_silu[tid + 64] = ce / (1.0f + __expf(-ce));
    }
    __syncthreads();
    const int j = tid;                                  // 0..255
    float acc = ln_b[j];
#pragma unroll 16
    for (int k = 0; k < 128; k++) acc += s_silu[k] * ln_w[k * 256 + j];
    g_ada[b * 256 + j] = acc;
}

// ---------------- kernel B: LayerNorm + modulate -> g_y -----------------------
// grid(1024), block(256). warp per row.
__global__ void ln_kernel(const float* __restrict__ x) {
    const int tid = threadIdx.x;
    const int warp = tid >> 5, lane = tid & 31;
    const int row = blockIdx.x * 8 + warp;
    const int b = row >> 12;

    const float4 xv = *(const float4*)(x + row * 128 + lane * 4);
    float sum = xv.x + xv.y + xv.z + xv.w;
    float sq  = xv.x * xv.x + xv.y * xv.y + xv.z * xv.z + xv.w * xv.w;
#pragma unroll
    for (int o = 16; o; o >>= 1) {
        sum += __shfl_xor_sync(FULL, sum, o);
        sq  += __shfl_xor_sync(FULL, sq, o);
    }
    const float mean = sum * (1.0f / 128.0f);
    const float var  = sq * (1.0f / 128.0f) - mean * mean;
    const float rstd = rsqrtf(var + 1e-5f);

    const float4 sc = *(const float4*)(g_ada + b * 256 + lane * 4);
    const float4 sh = *(const float4*)(g_ada + b * 256 + 128 + lane * 4);
    float4 yv;
    yv.x = (xv.x - mean) * rstd * (1.0f + sc.x) + sh.x;
    yv.y = (xv.y - mean) * rstd * (1.0f + sc.y) + sh.y;
    yv.z = (xv.z - mean) * rstd * (1.0f + sc.z) + sh.z;
    yv.w = (xv.w - mean) * rstd * (1.0f + sc.w) + sh.w;
    *(float4*)(g_y + row * 128 + lane * 4) = yv;
}

// ---------------- kernel C: qkv GEMM [8192,128]x[128,384] ---------------------
// grid(128,6), block(128). tile 64x64, thread 4x8, full K in smem, one sync.
__global__ void qkv_gemm(const float* __restrict__ W,
                         const float* __restrict__ bias) {
    __shared__ float sa[64 * 132];       // [m][k], pad 132
    __shared__ float sb[128 * 64];       // [k][n]
    const int tid = threadIdx.x;
    const int m0 = blockIdx.x * 64, n0 = blockIdx.y * 64;

#pragma unroll
    for (int r = 0; r < 16; r++) {
        const int id = tid + r * 128;
        const int row = id >> 5, j4 = id & 31;
        *(float4*)(sa + row * 132 + j4 * 4) =
            *(const float4*)(g_y + (m0 + row) * 128 + j4 * 4);
    }
#pragma unroll
    for (int r = 0; r < 16; r++) {
        const int id = tid + r * 128;
        const int kk = id >> 4, j4 = id & 15;
        *(float4*)(sb + kk * 64 + j4 * 4) =
            *(const float4*)(W + kk * 384 + n0 + j4 * 4);
    }
    __syncthreads();

    const int warp = tid >> 5, lane = tid & 31;
    const int rg = lane >> 3, cg = lane & 7;
    const int rowb = warp * 16 + rg * 4;

    float acc[4][8];
#pragma unroll
    for (int i = 0; i < 4; i++)
#pragma unroll
        for (int c = 0; c < 8; c++) acc[i][c] = 0.0f;

#pragma unroll 8
    for (int kk = 0; kk < 128; kk++) {
        const float a0 = sa[(rowb + 0) * 132 + kk];
        const float a1 = sa[(rowb + 1) * 132 + kk];
        const float a2 = sa[(rowb + 2) * 132 + kk];
        const float a3 = sa[(rowb + 3) * 132 + kk];
        const float4 b0 = *(const float4*)(sb + kk * 64 + cg * 8);
        const float4 b1 = *(const float4*)(sb + kk * 64 + cg * 8 + 4);
        acc[0][0] += a0 * b0.x; acc[0][1] += a0 * b0.y; acc[0][2] += a0 * b0.z; acc[0][3] += a0 * b0.w;
        acc[0][4] += a0 * b1.x; acc[0][5] += a0 * b1.y; acc[0][6] += a0 * b1.z; acc[0][7] += a0 * b1.w;
        acc[1][0] += a1 * b0.x; acc[1][1] += a1 * b0.y; acc[1][2] += a1 * b0.z; acc[1][3] += a1 * b0.w;
        acc[1][4] += a1 * b1.x; acc[1][5] += a1 * b1.y; acc[1][6] += a1 * b1.z; acc[1][7] += a1 * b1.w;
        acc[2][0] += a2 * b0.x; acc[2][1] += a2 * b0.y; acc[2][2] += a2 * b0.z; acc[2][3] += a2 * b0.w;
        acc[2][4] += a2 * b1.x; acc[2][5] += a2 * b1.y; acc[2][6] += a2 * b1.z; acc[2][7] += a2 * b1.w;
        acc[3][0] += a3 * b0.x; acc[3][1] += a3 * b0.y; acc[3][2] += a3 * b0.z; acc[3][3] += a3 * b0.w;
        acc[3][4] += a3 * b1.x; acc[3][5] += a3 * b1.y; acc[3][6] += a3 * b1.z; acc[3][7] += a3 * b1.w;
    }

    const float qscale = 0.17677669529663687f;   // 32^-0.5
#pragma unroll
    for (int i = 0; i < 4; i++) {
        const int row = m0 + rowb + i;
        const int bb = row >> 12, hh = (row >> 6) & 63, ww = row & 63;
#pragma unroll
        for (int half = 0; half < 2; half++) {
            const int j = n0 + cg * 8 + half * 4;        // global col, mult of 4
            const float4 bv = *(const float4*)(bias + j);
            float4 val;
            val.x = acc[i][half * 4 + 0] + bv.x;
            val.y = acc[i][half * 4 + 1] + bv.y;
            val.z = acc[i][half * 4 + 2] + bv.z;
            val.w = acc[i][half * 4 + 3] + bv.w;
            const int which = j >> 7;
            const int rem = j & 127;
            const int n = rem >> 5, d = rem & 31;
            const int idx = (((bb * 4 + n) * 64 + hh) * 64 + ww) * 32 + d;
            if (which == 0) {
                val.x *= qscale; val.y *= qscale; val.z *= qscale; val.w *= qscale;
                *(float4*)(g_q + idx) = val;
            } else if (which == 1) {
                *(float4*)(g_k + idx) = val;
            } else {
                *(float4*)(g_v + idx) = val;
            }
        }
    }
}

// ---------------- kernel D: 7x7 neighborhood attention, thread-per-query ------
// grid(16 h-tiles, 8 bn), block(256) = 4 h-rows x 64 w.
// K/V in smem, layout [row][col][d] with XOR swizzle on d-chunk (chunk^ (col&7))
// -> conflict-free LDS.128 for both staging and compute.
__global__ void natten_kernel(const float* __restrict__ rpb) {
    extern __shared__ float smem[];
    float* sk = smem;                 // up to 10*64*32 = 20480
    float* sv = smem + 20480;
    float* srpb = smem + 40960;       // 169

    const int tid = threadIdx.x;
    const int h0 = blockIdx.x * 4;
    const int bn = blockIdx.y;
    const int b = bn >> 2, n = bn & 3;
    const int base = bn * (64 * 64 * 32);

    const int hs0 = nb_start(h0);
    const int nrows = nb_start(h0 + 3) + 6 - hs0 + 1;   // 7..10

    // stage K/V (float4 chunks, swizzled)
    const int nchunks = nrows * 512;                     // rows*64*8
    for (int i = tid; i < nchunks; i += 256) {
        const int a = i >> 9;
        const int rem = i & 511;
        const int w = rem >> 3, j = rem & 7;
        const int g = base + (hs0 + a) * 2048 + w * 32 + j * 4;
        const int s4 = (a * 64 + w) * 8 + (j ^ (w & 7));
        ((float4*)sk)[s4] = *(const float4*)(g_k + g);
        ((float4*)sv)[s4] = *(const float4*)(g_v + g);
    }
    for (int i = tid; i < 169; i += 256) srpb[i] = rpb[n * 169 + i];
    __syncthreads();

    const int ih = tid >> 6;
    const int w = tid & 63;
    const int h = h0 + ih;
    const int ws = nb_start(w);
    const int hs_q = nb_start(h);
    const int arow0 = hs_q - hs0;
    const int rbase = (hs_q - h + 6) * 13 + (ws - w + 6);

    float4 q4[8];
    {
        const int qoff = base + h * 2048 + w * 32;
#pragma unroll
        for (int j = 0; j < 8; j++) q4[j] = *(const float4*)(g_q + qoff + 4 * j);
    }

    float4 acc4[8];
#pragma unroll
    for (int j = 0; j < 8; j++) acc4[j] = make_float4(0.f, 0.f, 0.f, 0.f);
    float m = -INFINITY, l = 0.0f;

#pragma unroll
    for (int a = 0; a < 7; a++) {
        const int row = arow0 + a;
        float sc[7];
#pragma unroll
        for (int c = 0; c < 7; c++) {
            const int col = ws + c;
            const float4* kp = ((const float4*)sk) + (row * 64 + col) * 8;
            const int sw = col & 7;
            float p0 = 0.f, p1 = 0.f, p2 = 0.f, p3 = 0.f;
#pragma unroll
            for (int j = 0; j < 8; j++) {
                const float4 kv = kp[j ^ sw];
                p0 += q4[j].x * kv.x;
                p1 += q4[j].y * kv.y;
                p2 += q4[j].z * kv.z;
                p3 += q4[j].w * kv.w;
            }
            sc[c] = (p0 + p1) + (p2 + p3) + srpb[rbase + a * 13 + c];
        }
        float rmax = sc[0];
#pragma unroll
        for (int c = 1; c < 7; c++) rmax = fmaxf(rmax, sc[c]);
        const float nm = fmaxf(m, rmax);
        const float corr = __expf(m - nm);
        float pc[7];
        float ps = 0.f;
#pragma unroll
        for (int c = 0; c < 7; c++) { pc[c] = __expf(sc[c] - nm); ps += pc[c]; }
        l = l * corr + ps;
        m = nm;

        const float4* vp = ((const float4*)sv) + (row * 64 + ws) * 8;
#pragma unroll
        for (int j = 0; j < 8; j++) {
            float4 av = acc4[j];
            av.x *= corr; av.y *= corr; av.z *= corr; av.w *= corr;
#pragma unroll
            for (int c = 0; c < 7; c++) {
                const int col = ws + c;
                const float4 vv = vp[c * 8 + (j ^ (col & 7))];
                av.x += pc[c] * vv.x;
                av.y += pc[c] * vv.y;
                av.z += pc[c] * vv.z;
                av.w += pc[c] * vv.w;
            }
            acc4[j] = av;
        }
    }

    const float inv = 1.0f / l;
    const int ob = ((b * 64 + h) * 64 + w) * 128 + n * 32;
#pragma unroll
    for (int j = 0; j < 8; j++) {
        float4 o = acc4[j];
        o.x *= inv; o.y *= inv; o.z *= inv; o.w *= inv;
        *(float4*)(g_att + ob + 4 * j) = o;
    }
}

// ---------------- kernel E: proj GEMM [8192,128]x[128,128] + bias -------------
// grid(128,2), block(128). Same scheme as qkv_gemm.
__global__ void proj_gemm(const float* __restrict__ W,
                          const float* __restrict__ bias,
                          float* __restrict__ out) {
    __shared__ float sa[64 * 132];
    __shared__ float sb[128 * 64];
    const int tid = threadIdx.x;
    const int m0 = blockIdx.x * 64, n0 = blockIdx.y * 64;

#pragma unroll
    for (int r = 0; r < 16; r++) {
        const int id = tid + r * 128;
        const int row = id >> 5, j4 = id & 31;
        *(float4*)(sa + row * 132 + j4 * 4) =
            *(const float4*)(g_att + (m0 + row) * 128 + j4 * 4);
    }
#pragma unroll
    for (int r = 0; r < 16; r++) {
        const int id = tid + r * 128;
        const int kk = id >> 4, j4 = id & 15;
        *(float4*)(sb + kk * 64 + j4 * 4) =
            *(const float4*)(W + kk * 128 + n0 + j4 * 4);
    }
    __syncthreads();

    const int warp = tid >> 5, lane = tid & 31;
    const int rg = lane >> 3, cg = lane & 7;
    const int rowb = warp * 16 + rg * 4;

    float acc[4][8];
#pragma unroll
    for (int i = 0; i < 4; i++)
#pragma unroll
        for (int c = 0; c < 8; c++) acc[i][c] = 0.0f;

#pragma unroll 8
    for (int kk = 0; kk < 128; kk++) {
        const float a0 = sa[(rowb + 0) * 132 + kk];
        const float a1 = sa[(rowb + 1) * 132 + kk];
        const float a2 = sa[(rowb + 2) * 132 + kk];
        const float a3 = sa[(rowb + 3) * 132 + kk];
        const float4 b0 = *(const float4*)(sb + kk * 64 + cg * 8);
        const float4 b1 = *(const float4*)(sb + kk * 64 + cg * 8 + 4);
        acc[0][0] += a0 * b0.x; acc[0][1] += a0 * b0.y; acc[0][2] += a0 * b0.z; acc[0][3] += a0 * b0.w;
        acc[0][4] += a0 * b1.x; acc[0][5] += a0 * b1.y; acc[0][6] += a0 * b1.z; acc[0][7] += a0 * b1.w;
        acc[1][0] += a1 * b0.x; acc[1][1] += a1 * b0.y; acc[1][2] += a1 * b0.z; acc[1][3] += a1 * b0.w;
        acc[1][4] += a1 * b1.x; acc[1][5] += a1 * b1.y; acc[1][6] += a1 * b1.z; acc[1][7] += a1 * b1.w;
        acc[2][0] += a2 * b0.x; acc[2][1] += a2 * b0.y; acc[2][2] += a2 * b0.z; acc[2][3] += a2 * b0.w;
        acc[2][4] += a2 * b1.x; acc[2][5] += a2 * b1.y; acc[2][6] += a2 * b1.z; acc[2][7] += a2 * b1.w;
        acc[3][0] += a3 * b0.x; acc[3][1] += a3 * b0.y; acc[3][2] += a3 * b0.z; acc[3][3] += a3 * b0.w;
        acc[3][4] += a3 * b1.x; acc[3][5] += a3 * b1.y; acc[3][6] += a3 * b1.z; acc[3][7] += a3 * b1.w;
    }

#pragma unroll
    for (int i = 0; i < 4; i++) {
        const int row = m0 + rowb + i;
#pragma unroll
        for (int half = 0; half < 2; half++) {
            const int j = n0 + cg * 8 + half * 4;
            const float4 bv = *(const float4*)(bias + j);
            float4 val;
            val.x = acc[i][half * 4 + 0] + bv.x;
            val.y = acc[i][half * 4 + 1] + bv.y;
            val.z = acc[i][half * 4 + 2] + bv.z;
            val.w = acc[i][half * 4 + 3] + bv.w;
            *(float4*)(out + row * 128 + j) = val;
        }
    }
}

// ---------------- launch ------------------------------------------------------
extern "C" void kernel_launch(void* const* d_in, const int* in_sizes, int n_in,
                              void* d_out, int out_size) {
    const float* x      = (const float*)d_in[0];
    // d_in[1] = cond (unused)
    const int*   t      = (const int*)d_in[2];
    const float* ln_w   = (const float*)d_in[3];
    const float* ln_b   = (const float*)d_in[4];
    const float* qkv_w  = (const float*)d_in[5];
    const float* qkv_b  = (const float*)d_in[6];
    const float* rpb    = (const float*)d_in[7];
    const float* proj_w = (const float*)d_in[8];
    const float* proj_b = (const float*)d_in[9];
    float* out = (float*)d_out;

    const int natten_smem = (2 * 20480 + 176) * 4;   // 164,544 B
    cudaFuncSetAttribute(natten_kernel,
                         cudaFuncAttributeMaxDynamicSharedMemorySize, natten_smem);

    adaln_kernel<<<2, 256>>>(t, ln_w, ln_b);
    ln_kernel<<<1024, 256>>>(x);
    qkv_gemm<<<dim3(128, 6), 128>>>(qkv_w, qkv_b);
    natten_kernel<<<dim3(16, 8), 256, natten_smem>>>(rpb);
    proj_gemm<<<dim3(128, 2), 128>>>(proj_w, proj_b, out);
}